// round 14
// baseline (speedup 1.0000x reference)
#include <cuda_runtime.h>
#include <cstdint>

#define BH 16
#define NS 256
#define DH 64
#define EPSF 1.1920929e-07f

// ---------------- scratch (device globals; no allocs) ----------------
__device__ __align__(16) float g_qkv[512 * 2560];
__device__ __align__(16) float g_qn [BH * NS * DH];
__device__ __align__(16) float g_k1 [BH * NS * DH];
__device__ __align__(16) float g_k2 [BH * NS * DH];
__device__ __align__(16) float g_v1t[BH * DH * NS];
__device__ __align__(16) float g_v2t[BH * DH * NS];
__device__ __align__(16) float g_e1 [BH * NS * NS];
__device__ __align__(16) float g_e2 [BH * NS * NS];
__device__ __align__(16) float g_e3 [BH * NS * NS];
__device__ __align__(16) float g_numP[2][BH * NS * DH];
__device__ __align__(16) float g_denP[2][BH * NS];
__device__ __align__(16) float g_o  [512 * 512];

__device__ __forceinline__ uint32_t cvt_tf32(float x) {
    uint32_t r; asm("cvt.rna.tf32.f32 %0, %1;" : "=r"(r) : "f"(x)); return r;
}
__device__ __forceinline__ uint32_t smem_u32(const void* p) {
    uint32_t a;
    asm("{ .reg .u64 t; cvta.to.shared.u64 t, %1; cvt.u32.u64 %0, t; }" : "=r"(a) : "l"(p));
    return a;
}
__device__ __forceinline__ void mma_tf32(float* c,
        uint32_t a0, uint32_t a1, uint32_t a2, uint32_t a3,
        uint32_t b0, uint32_t b1) {
    asm volatile("mma.sync.aligned.m16n8k8.row.col.f32.tf32.tf32.f32 "
        "{%0,%1,%2,%3}, {%4,%5,%6,%7}, {%8,%9}, {%0,%1,%2,%3};"
        : "+f"(c[0]), "+f"(c[1]), "+f"(c[2]), "+f"(c[3])
        : "r"(a0), "r"(a1), "r"(a2), "r"(a3), "r"(b0), "r"(b1));
}
__device__ __forceinline__ void ldsm_x4(uint32_t& r0, uint32_t& r1,
                                        uint32_t& r2, uint32_t& r3, uint32_t a) {
    asm volatile("ldmatrix.sync.aligned.m8n8.x4.shared.b16 {%0,%1,%2,%3}, [%4];"
                 : "=r"(r0), "=r"(r1), "=r"(r2), "=r"(r3) : "r"(a));
}

// ---------------- generic SGEMM: C[M,N] = A[M,K] @ B[K,N] ----------------
__global__ void sgemm128x64(const float* __restrict__ A, const float* __restrict__ B,
                            float* __restrict__ C, int M, int N, int K) {
    __shared__ float As[16][128];
    __shared__ float Bs[16][64];
    int t = threadIdx.x;
    int tx = t & 15, ty = t >> 4;
    int m0 = blockIdx.y * 128, n0 = blockIdx.x * 64;

    float acc[8][4];
#pragma unroll
    for (int i = 0; i < 8; i++)
#pragma unroll
        for (int j = 0; j < 4; j++) acc[i][j] = 0.f;

    for (int kt = 0; kt < K; kt += 16) {
#pragma unroll
        for (int q = 0; q < 2; q++) {
            int lin = t + q * 256;
            int m = lin & 127, kq = lin >> 7;
            float4 v = *(const float4*)&A[(size_t)(m0 + m) * K + kt + kq * 4];
            As[kq * 4 + 0][m] = v.x; As[kq * 4 + 1][m] = v.y;
            As[kq * 4 + 2][m] = v.z; As[kq * 4 + 3][m] = v.w;
        }
        {
            int kk = t >> 4, nq = t & 15;
            float4 v = *(const float4*)&B[(size_t)(kt + kk) * N + n0 + nq * 4];
            *(float4*)&Bs[kk][nq * 4] = v;
        }
        __syncthreads();
#pragma unroll
        for (int kk = 0; kk < 16; kk++) {
            float4 b = *(float4*)&Bs[kk][tx * 4];
            float a[8];
#pragma unroll
            for (int i = 0; i < 8; i++) a[i] = As[kk][ty * 8 + i];
#pragma unroll
            for (int i = 0; i < 8; i++) {
                acc[i][0] += a[i] * b.x; acc[i][1] += a[i] * b.y;
                acc[i][2] += a[i] * b.z; acc[i][3] += a[i] * b.w;
            }
        }
        __syncthreads();
    }
#pragma unroll
    for (int i = 0; i < 8; i++) {
        float4 v = make_float4(acc[i][0], acc[i][1], acc[i][2], acc[i][3]);
        *(float4*)&C[(size_t)(m0 + ty * 8 + i) * N + n0 + tx * 4] = v;
    }
}

// ---------------- split + rmsnorm + pack ----------------
__global__ void pack_norm(const float* __restrict__ qw,
                          const float* __restrict__ k1w,
                          const float* __restrict__ k2w) {
    int blk = blockIdx.x;
    int bh = blk >> 8, n = blk & 255;
    int b = bh >> 3, h = bh & 7;
    int dd = threadIdx.x;
    size_t base = (size_t)(b * 256 + n) * 2560 + h * 64 + dd;
    float q  = g_qkv[base];
    float k1 = g_qkv[base + 512];
    float k2 = g_qkv[base + 1024];
    float v1 = g_qkv[base + 1536];
    float v2 = g_qkv[base + 2048];

    __shared__ float sw[3][2];
    float sq = q * q, s1 = k1 * k1, s2 = k2 * k2;
#pragma unroll
    for (int o = 16; o; o >>= 1) {
        sq += __shfl_xor_sync(0xffffffffu, sq, o);
        s1 += __shfl_xor_sync(0xffffffffu, s1, o);
        s2 += __shfl_xor_sync(0xffffffffu, s2, o);
    }
    int w = dd >> 5;
    if ((dd & 31) == 0) { sw[0][w] = sq; sw[1][w] = s1; sw[2][w] = s2; }
    __syncthreads();
    float rq = rsqrtf((sw[0][0] + sw[0][1]) * (1.f / 64.f) + EPSF);
    float r1 = rsqrtf((sw[1][0] + sw[1][1]) * (1.f / 64.f) + EPSF);
    float r2 = rsqrtf((sw[2][0] + sw[2][1]) * (1.f / 64.f) + EPSF);

    int rb = bh * NS * DH + n * DH + dd;
    g_qn[rb] = q * rq * qw[dd] * 0.125f;
    g_k1[rb] = k1 * r1 * k1w[dd];
    g_k2[rb] = k2 * r2 * k2w[dd];
    g_v1t[bh * DH * NS + dd * NS + n] = v1;
    g_v2t[bh * DH * NS + dd * NS + n] = v2;
}

// ---------------- sims: e = exp(clip(scale * L @ R^T)) ----------------
__global__ void sims_kernel() {
    int z = blockIdx.z;
    int bh = z / 3, mat = z % 3;
    const float* L = ((mat == 2) ? g_k1 : g_qn) + bh * NS * DH;
    const float* R = ((mat == 0) ? g_k1 : g_k2) + bh * NS * DH;
    float* C = ((mat == 0) ? g_e1 : (mat == 1) ? g_e2 : g_e3) + (size_t)bh * NS * NS;
    float scale = (mat == 2) ? 0.125f : 1.f;

    __shared__ float As[16][128];
    __shared__ float Bs[16][64];
    int t = threadIdx.x, tx = t & 15, ty = t >> 4;
    int m0 = blockIdx.y * 128, n0 = blockIdx.x * 64;

    float acc[8][4];
#pragma unroll
    for (int i = 0; i < 8; i++)
#pragma unroll
        for (int j = 0; j < 4; j++) acc[i][j] = 0.f;

    for (int kt = 0; kt < 64; kt += 16) {
#pragma unroll
        for (int q = 0; q < 2; q++) {
            int lin = t + q * 256;
            int m = lin & 127, kq = lin >> 7;
            float4 v = *(const float4*)&L[(m0 + m) * 64 + kt + kq * 4];
            As[kq * 4 + 0][m] = v.x; As[kq * 4 + 1][m] = v.y;
            As[kq * 4 + 2][m] = v.z; As[kq * 4 + 3][m] = v.w;
        }
        {
            int n = t & 63, kq = t >> 6;
            float4 v = *(const float4*)&R[(n0 + n) * 64 + kt + kq * 4];
            Bs[kq * 4 + 0][n] = v.x; Bs[kq * 4 + 1][n] = v.y;
            Bs[kq * 4 + 2][n] = v.z; Bs[kq * 4 + 3][n] = v.w;
        }
        __syncthreads();
#pragma unroll
        for (int kk = 0; kk < 16; kk++) {
            float4 b = *(float4*)&Bs[kk][tx * 4];
            float a[8];
#pragma unroll
            for (int i = 0; i < 8; i++) a[i] = As[kk][ty * 8 + i];
#pragma unroll
            for (int i = 0; i < 8; i++) {
                acc[i][0] += a[i] * b.x; acc[i][1] += a[i] * b.y;
                acc[i][2] += a[i] * b.z; acc[i][3] += a[i] * b.w;
            }
        }
        __syncthreads();
    }
#pragma unroll
    for (int i = 0; i < 8; i++) {
        float4 v;
        v.x = __expf(fminf(40.f, fmaxf(-40.f, acc[i][0] * scale)));
        v.y = __expf(fminf(40.f, fmaxf(-40.f, acc[i][1] * scale)));
        v.z = __expf(fminf(40.f, fmaxf(-40.f, acc[i][2] * scale)));
        v.w = __expf(fminf(40.f, fmaxf(-40.f, acc[i][3] * scale)));
        *(float4*)&C[(size_t)(m0 + ty * 8 + i) * NS + n0 + tx * 4] = v;
    }
}

// ---------------- heavy: mma.sync tf32 + ldmatrix, register-diet ----------------
// CTA (dg, ib, jb, bh): tile 64(i) x 128(j), 256 threads, 8 warps,
// warp grid 2(i) x 4(j), warp tile 32x32.
// Register diet: e2 half0 in regs (32), half1 in SMEM (raw fp32); A single
// buffer. Frees ~60 regs so the 1-step LDSM prefetch can actually live in RF.
#define BPCH 260
#define APCH 132
#define B_OFF 0
#define A_OFF 133120
#define E2H_OFF 166912
#define RED_OFF 199680
#define V2_OFF 200704
#define SMEM_SZ 201728

// one k-half mainloop with 1-step fragment prefetch (A always at offset 0)
#define HALF_LOOP(BOFS)                                                               \
    {                                                                                 \
        uint32_t fa[2][8], fb[2][8];                                                  \
        ldsm_x4(fa[0][0], fa[0][1], fa[0][2], fa[0][3], aBase);                       \
        ldsm_x4(fa[0][4], fa[0][5], fa[0][6], fa[0][7], aBase + 8448);                \
        ldsm_x4(fb[0][0], fb[0][1], fb[0][2], fb[0][3], bBase + (BOFS));              \
        ldsm_x4(fb[0][4], fb[0][5], fb[0][6], fb[0][7], bBase + (BOFS) + 16640);      \
        _Pragma("unroll")                                                             \
        for (int ks = 0; ks < 16; ks++) {                                             \
            const int cur = ks & 1, nxt = cur ^ 1;                                    \
            if (ks < 15) {                                                            \
                uint32_t ko = (uint32_t)((ks + 1) * 32);                              \
                ldsm_x4(fa[nxt][0], fa[nxt][1], fa[nxt][2], fa[nxt][3],               \
                        aBase + ko);                                                  \
                ldsm_x4(fa[nxt][4], fa[nxt][5], fa[nxt][6], fa[nxt][7],               \
                        aBase + 8448 + ko);                                           \
                ldsm_x4(fb[nxt][0], fb[nxt][1], fb[nxt][2], fb[nxt][3],               \
                        bBase + (BOFS) + ko);                                         \
                ldsm_x4(fb[nxt][4], fb[nxt][5], fb[nxt][6], fb[nxt][7],               \
                        bBase + (BOFS) + 16640 + ko);                                 \
            }                                                                         \
            mma_tf32(acc[0][0], fa[cur][0], fa[cur][1], fa[cur][2], fa[cur][3],       \
                     fb[cur][0], fb[cur][1]);                                         \
            mma_tf32(acc[0][1], fa[cur][0], fa[cur][1], fa[cur][2], fa[cur][3],       \
                     fb[cur][2], fb[cur][3]);                                         \
            mma_tf32(acc[0][2], fa[cur][0], fa[cur][1], fa[cur][2], fa[cur][3],       \
                     fb[cur][4], fb[cur][5]);                                         \
            mma_tf32(acc[0][3], fa[cur][0], fa[cur][1], fa[cur][2], fa[cur][3],       \
                     fb[cur][6], fb[cur][7]);                                         \
            mma_tf32(acc[1][0], fa[cur][4], fa[cur][5], fa[cur][6], fa[cur][7],       \
                     fb[cur][0], fb[cur][1]);                                         \
            mma_tf32(acc[1][1], fa[cur][4], fa[cur][5], fa[cur][6], fa[cur][7],       \
                     fb[cur][2], fb[cur][3]);                                         \
            mma_tf32(acc[1][2], fa[cur][4], fa[cur][5], fa[cur][6], fa[cur][7],       \
                     fb[cur][4], fb[cur][5]);                                         \
            mma_tf32(acc[1][3], fa[cur][4], fa[cur][5], fa[cur][6], fa[cur][7],       \
                     fb[cur][6], fb[cur][7]);                                         \
        }                                                                             \
    }

__global__ void __launch_bounds__(256, 1) heavy_mma() {
    extern __shared__ __align__(16) char smem[];
    const uint32_t sb = smem_u32(smem);
    uint32_t* Bu  = (uint32_t*)(smem + B_OFF);
    uint32_t* Au  = (uint32_t*)(smem + A_OFF);
    float*    E2h = (float*)(smem + E2H_OFF);   // raw e2, k in [128,256)
    float*    red = (float*)(smem + RED_OFF);
    float*    v2s = (float*)(smem + V2_OFF);

    int t = threadIdx.x, lane = t & 31, wid = t >> 5;
    int wi = wid >> 2, wj = wid & 3;            // 2(i) x 4(j)
    int i0 = wi * 32, j0 = wj * 32;
    int dg = blockIdx.x;                        // 0..4, 13 channels each
    int ib = blockIdx.y >> 1, jb = blockIdx.y & 1;
    int bh = blockIdx.z;

    const float* e2p = g_e2 + (size_t)bh * 65536 + (size_t)(ib * 64) * 256;
    const float* e3p = g_e3 + (size_t)bh * 65536 + (size_t)(jb * 128) * 256;
    const float* e1p = g_e1 + (size_t)bh * 65536 + (size_t)(ib * 64) * 256 + jb * 128;
    const float* v1b = g_v1t + (size_t)bh * DH * NS;
    const float* v2b = g_v2t + (size_t)bh * DH * NS;

    // ---- B static: tf32(e3) [128 x 256] pitch 260, built once ----
    for (int idx = t; idx < 8192; idx += 256) {   // 128 rows x 64 float4
        int r = idx >> 6, q = (idx & 63) << 2;
        float4 b = *(const float4*)&e3p[r * 256 + q];
        uint4 u;
        u.x = cvt_tf32(b.x); u.y = cvt_tf32(b.y);
        u.z = cvt_tf32(b.z); u.w = cvt_tf32(b.w);
        *(uint4*)&Bu[r * BPCH + q] = u;
    }

    // ---- e2 half0 -> registers; e2 half1 -> smem (raw fp32) ----
    float4 st0[8];
#pragma unroll
    for (int q = 0; q < 8; q++) {
        int row = wid + 8 * q;
        st0[q] = *(const float4*)&e2p[row * 256 + lane * 4];
    }
    for (int idx = t; idx < 2048; idx += 256) {   // 64 rows x 32 float4
        int r = idx >> 5, q = (idx & 31) << 2;
        float4 a = *(const float4*)&e2p[r * 256 + 128 + q];
        *(float4*)&E2h[r * 128 + q] = a;
    }

    // ---- e1 fragments in registers (d-independent) ----
    float er[2][4][4];
#pragma unroll
    for (int mt = 0; mt < 2; mt++) {
        int ir = i0 + mt * 16 + (lane >> 2);
#pragma unroll
        for (int nt = 0; nt < 4; nt++) {
            int j = j0 + nt * 8 + (lane & 3) * 2;
            float2 w0 = *(const float2*)&e1p[(size_t)ir * 256 + j];
            float2 w1 = *(const float2*)&e1p[(size_t)(ir + 8) * 256 + j];
            er[mt][nt][0] = w0.x; er[mt][nt][1] = w0.y;
            er[mt][nt][2] = w1.x; er[mt][nt][3] = w1.y;
        }
    }

    // ---- v2 smem + v1 regs for channel 0 ----
    int d0 = dg * 13;
    v2s[t] = v2b[(size_t)d0 * NS + t];
    float vr0[4], vr1[4];
#pragma unroll
    for (int nt = 0; nt < 4; nt++) {
        int jg = jb * 128 + j0 + nt * 8 + (lane & 3) * 2;
        vr0[nt] = v1b[(size_t)d0 * NS + jg];
        vr1[nt] = v1b[(size_t)d0 * NS + jg + 1];
    }

    // ---- ldmatrix lane addresses ----
    int lr = lane & 7;
    uint32_t aRow = (uint32_t)(i0 + ((lane >> 3) & 1) * 8 + lr);
    uint32_t aK   = (uint32_t)((lane >> 4) * 4);
    uint32_t aBase = sb + A_OFF + (aRow * APCH + aK) * 4;  // +mt*8448 +ks*32
    uint32_t bRow = (uint32_t)(j0 + ((lane >> 4) & 1) * 8 + lr);
    uint32_t bK   = (uint32_t)(((lane >> 3) & 1) * 4);
    uint32_t bBase = sb + B_OFF + (bRow * BPCH + bK) * 4;  // +ntp*16640 +half*512 +ks*32

    __syncthreads();   // B + e2 smem + v2s ready

    float acc[2][4][4];

#pragma unroll 1
    for (int ch = 0; ch < 13; ch++) {
        int d = dg * 13 + ch;

        // ===== half 0: build A = tf32(e2*v2) from regs =====
#pragma unroll
        for (int q = 0; q < 8; q++) {
            int row = wid + 8 * q;
            float4 a = st0[q];
            float4 w = *(const float4*)&v2s[lane * 4];
            uint4 u;
            u.x = cvt_tf32(a.x * w.x); u.y = cvt_tf32(a.y * w.y);
            u.z = cvt_tf32(a.z * w.z); u.w = cvt_tf32(a.w * w.w);
            *(uint4*)&Au[row * APCH + lane * 4] = u;
        }
        __syncthreads();

#pragma unroll
        for (int m = 0; m < 2; m++)
#pragma unroll
            for (int n = 0; n < 4; n++)
#pragma unroll
                for (int c = 0; c < 4; c++) acc[m][n][c] = 0.f;

        HALF_LOOP(0u)
        __syncthreads();   // all warps done reading A before overwrite

        // ===== half 1: build A from e2 smem =====
#pragma unroll
        for (int q = 0; q < 8; q++) {
            int row = wid + 8 * q;
            float4 a = *(const float4*)&E2h[row * 128 + lane * 4];
            float4 w = *(const float4*)&v2s[128 + lane * 4];
            uint4 u;
            u.x = cvt_tf32(a.x * w.x); u.y = cvt_tf32(a.y * w.y);
            u.z = cvt_tf32(a.z * w.z); u.w = cvt_tf32(a.w * w.w);
            *(uint4*)&Au[row * APCH + lane * 4] = u;
        }
        __syncthreads();

        HALF_LOOP(512u)

        // ===== epilogue: partial[i] = sum_j e1*v1*G =====
#pragma unroll
        for (int mt = 0; mt < 2; mt++) {
            float p0 = 0.f, p1 = 0.f;
#pragma unroll
            for (int nt = 0; nt < 4; nt++) {
                p0 += acc[mt][nt][0] * er[mt][nt][0] * vr0[nt]
                    + acc[mt][nt][1] * er[mt][nt][1] * vr1[nt];
                p1 += acc[mt][nt][2] * er[mt][nt][2] * vr0[nt]
                    + acc[mt][nt][3] * er[mt][nt][3] * vr1[nt];
            }
            p0 += __shfl_xor_sync(0xffffffffu, p0, 1);
            p0 += __shfl_xor_sync(0xffffffffu, p0, 2);
            p1 += __shfl_xor_sync(0xffffffffu, p1, 1);
            p1 += __shfl_xor_sync(0xffffffffu, p1, 2);
            if ((lane & 3) == 0) {
                int il = i0 + mt * 16 + (lane >> 2);
                red[il * 4 + wj] = p0;
                red[(il + 8) * 4 + wj] = p1;
            }
        }
        __syncthreads();

        // final store + stage next channel's v1/v2
        if (t < 64) {
            float s = red[t * 4] + red[t * 4 + 1] + red[t * 4 + 2] + red[t * 4 + 3];
            int ig = ib * 64 + t;
            if (d < 64) g_numP[jb][((size_t)bh * NS + ig) * DH + d] = s;
            else        g_denP[jb][(size_t)bh * NS + ig] = s;
        }
        int d2 = d + 1;
        v2s[t] = (d2 < 64) ? v2b[(size_t)d2 * NS + t] : 1.f;
#pragma unroll
        for (int nt = 0; nt < 4; nt++) {
            int jg = jb * 128 + j0 + nt * 8 + (lane & 3) * 2;
            vr0[nt] = (d2 < 64) ? v1b[(size_t)d2 * NS + jg] : 1.f;
            vr1[nt] = (d2 < 64) ? v1b[(size_t)d2 * NS + jg + 1] : 1.f;
        }
        __syncthreads();
    }
}

// ---------------- normalize: combine 2 jb partials, o = num/den ----------------
__global__ void normalize_kernel() {
    int idx = blockIdx.x * 256 + threadIdx.x;   // 0..262143
    int dd = idx & 63;
    int i  = (idx >> 6) & 255;
    int bh = idx >> 14;
    int b = bh >> 3, h = bh & 7;
    float num = g_numP[0][idx] + g_numP[1][idx];
    float den = g_denP[0][bh * NS + i] + g_denP[1][bh * NS + i];
    g_o[(size_t)(b * 256 + i) * 512 + h * 64 + dd] = num / den;
}

extern "C" void kernel_launch(void* const* d_in, const int* in_sizes, int n_in,
                              void* d_out, int out_size) {
    const float* x     = (const float*)d_in[0];
    const float* w_qkv = (const float*)d_in[1];
    const float* w_out = (const float*)d_in[2];
    const float* qw    = (const float*)d_in[3];
    const float* k1w   = (const float*)d_in[4];
    const float* k2w   = (const float*)d_in[5];
    float* out = (float*)d_out;

    float *qkv_p = nullptr, *o_p = nullptr;
    cudaGetSymbolAddress((void**)&qkv_p, g_qkv);
    cudaGetSymbolAddress((void**)&o_p, g_o);

    cudaFuncSetAttribute(heavy_mma, cudaFuncAttributeMaxDynamicSharedMemorySize, SMEM_SZ);

    // 1) qkv = x @ w_qkv   [512,512]@[512,2560]
    sgemm128x64<<<dim3(40, 4), 256>>>(x, w_qkv, qkv_p, 512, 2560, 512);
    // 2) split + rmsnorm + pack
    pack_norm<<<4096, 64>>>(qw, k1w, k2w);
    // 3) e1/e2/e3
    sims_kernel<<<dim3(4, 2, 48), 256>>>();
    // 4) heavy: 5 dgroups x (ib 4 x jb 2) x bh 16 = 640 CTAs
    heavy_mma<<<dim3(5, 8, 16), 256, SMEM_SZ>>>();
    // 5) normalize (sum 2 jb partials)
    normalize_kernel<<<1024, 256>>>();
    // 6) out = o @ w_out   [512,512]@[512,512]
    sgemm128x64<<<dim3(8, 4), 256>>>(o_p, w_out, out, 512, 512, 512);
}

// round 15
// speedup vs baseline: 1.1294x; 1.1294x over previous
#include <cuda_runtime.h>
#include <cstdint>

#define BH 16
#define NS 256
#define DH 64
#define EPSF 1.1920929e-07f

// ---------------- scratch (device globals; no allocs) ----------------
__device__ __align__(16) float g_qkv[512 * 2560];
__device__ __align__(16) float g_qn [BH * NS * DH];
__device__ __align__(16) float g_k1 [BH * NS * DH];
__device__ __align__(16) float g_k2 [BH * NS * DH];
__device__ __align__(16) float g_v1t[BH * DH * NS];
__device__ __align__(16) float g_v2t[BH * DH * NS];
__device__ __align__(16) float g_e1 [BH * NS * NS];
__device__ __align__(16) float g_e2 [BH * NS * NS];
__device__ __align__(16) float g_e3 [BH * NS * NS];
__device__ __align__(16) float g_numP[2][BH * NS * DH];
__device__ __align__(16) float g_denP[2][BH * NS];
__device__ __align__(16) float g_o  [512 * 512];

__device__ __forceinline__ uint32_t cvt_tf32(float x) {
    uint32_t r; asm("cvt.rna.tf32.f32 %0, %1;" : "=r"(r) : "f"(x)); return r;
}
__device__ __forceinline__ uint32_t smem_u32(const void* p) {
    uint32_t a;
    asm("{ .reg .u64 t; cvta.to.shared.u64 t, %1; cvt.u32.u64 %0, t; }" : "=r"(a) : "l"(p));
    return a;
}
__device__ __forceinline__ void mma_tf32(float* c,
        uint32_t a0, uint32_t a1, uint32_t a2, uint32_t a3,
        uint32_t b0, uint32_t b1) {
    asm volatile("mma.sync.aligned.m16n8k8.row.col.f32.tf32.tf32.f32 "
        "{%0,%1,%2,%3}, {%4,%5,%6,%7}, {%8,%9}, {%0,%1,%2,%3};"
        : "+f"(c[0]), "+f"(c[1]), "+f"(c[2]), "+f"(c[3])
        : "r"(a0), "r"(a1), "r"(a2), "r"(a3), "r"(b0), "r"(b1));
}
__device__ __forceinline__ void ldsm_x4(uint32_t& r0, uint32_t& r1,
                                        uint32_t& r2, uint32_t& r3, uint32_t a) {
    asm volatile("ldmatrix.sync.aligned.m8n8.x4.shared.b16 {%0,%1,%2,%3}, [%4];"
                 : "=r"(r0), "=r"(r1), "=r"(r2), "=r"(r3) : "r"(a));
}

// ---------------- SGEMM 64x64 tiles: C[M,N] = A[M,K] @ B[K,N] ----------------
__global__ void sgemm64x64(const float* __restrict__ A, const float* __restrict__ B,
                           float* __restrict__ C, int M, int N, int K) {
    __shared__ float As[16][64];
    __shared__ float Bs[16][64];
    int t = threadIdx.x;
    int tx = t & 15, ty = t >> 4;     // 16 x 16 threads, micro 4x4
    int m0 = blockIdx.y * 64, n0 = blockIdx.x * 64;

    float acc[4][4];
#pragma unroll
    for (int i = 0; i < 4; i++)
#pragma unroll
        for (int j = 0; j < 4; j++) acc[i][j] = 0.f;

    for (int kt = 0; kt < K; kt += 16) {
        {
            int m = t & 63, kq = t >> 6;    // kq 0..3
            float4 v = *(const float4*)&A[(size_t)(m0 + m) * K + kt + kq * 4];
            As[kq * 4 + 0][m] = v.x; As[kq * 4 + 1][m] = v.y;
            As[kq * 4 + 2][m] = v.z; As[kq * 4 + 3][m] = v.w;
        }
        {
            int kk = t >> 4, nq = t & 15;
            float4 v = *(const float4*)&B[(size_t)(kt + kk) * N + n0 + nq * 4];
            *(float4*)&Bs[kk][nq * 4] = v;
        }
        __syncthreads();
#pragma unroll
        for (int kk = 0; kk < 16; kk++) {
            float4 b = *(float4*)&Bs[kk][tx * 4];
            float a[4];
#pragma unroll
            for (int i = 0; i < 4; i++) a[i] = As[kk][ty * 4 + i];
#pragma unroll
            for (int i = 0; i < 4; i++) {
                acc[i][0] += a[i] * b.x; acc[i][1] += a[i] * b.y;
                acc[i][2] += a[i] * b.z; acc[i][3] += a[i] * b.w;
            }
        }
        __syncthreads();
    }
#pragma unroll
    for (int i = 0; i < 4; i++) {
        float4 v = make_float4(acc[i][0], acc[i][1], acc[i][2], acc[i][3]);
        *(float4*)&C[(size_t)(m0 + ty * 4 + i) * N + n0 + tx * 4] = v;
    }
}

// ---------------- split + rmsnorm + pack: warp per (bh,n) row ----------------
__global__ void pack_norm(const float* __restrict__ qw,
                          const float* __restrict__ k1w,
                          const float* __restrict__ k2w) {
    int row = blockIdx.x * 8 + (threadIdx.x >> 5);   // 0..4095
    int lane = threadIdx.x & 31;
    int bh = row >> 8, n = row & 255;
    int b = bh >> 3, h = bh & 7;
    size_t base = (size_t)(b * 256 + n) * 2560 + h * 64;

    float q0  = g_qkv[base + lane],        q1  = g_qkv[base + lane + 32];
    float k10 = g_qkv[base + 512 + lane],  k11 = g_qkv[base + 512 + lane + 32];
    float k20 = g_qkv[base + 1024 + lane], k21 = g_qkv[base + 1024 + lane + 32];
    float v10 = g_qkv[base + 1536 + lane], v11 = g_qkv[base + 1536 + lane + 32];
    float v20 = g_qkv[base + 2048 + lane], v21 = g_qkv[base + 2048 + lane + 32];

    float sq = q0 * q0 + q1 * q1;
    float s1 = k10 * k10 + k11 * k11;
    float s2 = k20 * k20 + k21 * k21;
#pragma unroll
    for (int o = 16; o; o >>= 1) {
        sq += __shfl_xor_sync(0xffffffffu, sq, o);
        s1 += __shfl_xor_sync(0xffffffffu, s1, o);
        s2 += __shfl_xor_sync(0xffffffffu, s2, o);
    }
    float rq = rsqrtf(sq * (1.f / 64.f) + EPSF);
    float r1 = rsqrtf(s1 * (1.f / 64.f) + EPSF);
    float r2 = rsqrtf(s2 * (1.f / 64.f) + EPSF);

    int rb = bh * NS * DH + n * DH;
    g_qn[rb + lane]      = q0 * rq * qw[lane] * 0.125f;
    g_qn[rb + lane + 32] = q1 * rq * qw[lane + 32] * 0.125f;
    g_k1[rb + lane]      = k10 * r1 * k1w[lane];
    g_k1[rb + lane + 32] = k11 * r1 * k1w[lane + 32];
    g_k2[rb + lane]      = k20 * r2 * k2w[lane];
    g_k2[rb + lane + 32] = k21 * r2 * k2w[lane + 32];
    int vb = bh * DH * NS + n;
    g_v1t[vb + lane * NS]        = v10;
    g_v1t[vb + (lane + 32) * NS] = v11;
    g_v2t[vb + lane * NS]        = v20;
    g_v2t[vb + (lane + 32) * NS] = v21;
}

// ---------------- sims: e = exp(clip(scale * L @ R^T)) ----------------
__global__ void sims_kernel() {
    int z = blockIdx.z;
    int bh = z / 3, mat = z % 3;
    const float* L = ((mat == 2) ? g_k1 : g_qn) + bh * NS * DH;
    const float* R = ((mat == 0) ? g_k1 : g_k2) + bh * NS * DH;
    float* C = ((mat == 0) ? g_e1 : (mat == 1) ? g_e2 : g_e3) + (size_t)bh * NS * NS;
    float scale = (mat == 2) ? 0.125f : 1.f;

    __shared__ float As[16][128];
    __shared__ float Bs[16][64];
    int t = threadIdx.x, tx = t & 15, ty = t >> 4;
    int m0 = blockIdx.y * 128, n0 = blockIdx.x * 64;

    float acc[8][4];
#pragma unroll
    for (int i = 0; i < 8; i++)
#pragma unroll
        for (int j = 0; j < 4; j++) acc[i][j] = 0.f;

    for (int kt = 0; kt < 64; kt += 16) {
#pragma unroll
        for (int q = 0; q < 2; q++) {
            int lin = t + q * 256;
            int m = lin & 127, kq = lin >> 7;
            float4 v = *(const float4*)&L[(m0 + m) * 64 + kt + kq * 4];
            As[kq * 4 + 0][m] = v.x; As[kq * 4 + 1][m] = v.y;
            As[kq * 4 + 2][m] = v.z; As[kq * 4 + 3][m] = v.w;
        }
        {
            int n = t & 63, kq = t >> 6;
            float4 v = *(const float4*)&R[(n0 + n) * 64 + kt + kq * 4];
            Bs[kq * 4 + 0][n] = v.x; Bs[kq * 4 + 1][n] = v.y;
            Bs[kq * 4 + 2][n] = v.z; Bs[kq * 4 + 3][n] = v.w;
        }
        __syncthreads();
#pragma unroll
        for (int kk = 0; kk < 16; kk++) {
            float4 b = *(float4*)&Bs[kk][tx * 4];
            float a[8];
#pragma unroll
            for (int i = 0; i < 8; i++) a[i] = As[kk][ty * 8 + i];
#pragma unroll
            for (int i = 0; i < 8; i++) {
                acc[i][0] += a[i] * b.x; acc[i][1] += a[i] * b.y;
                acc[i][2] += a[i] * b.z; acc[i][3] += a[i] * b.w;
            }
        }
        __syncthreads();
    }
#pragma unroll
    for (int i = 0; i < 8; i++) {
        float4 v;
        v.x = __expf(fminf(40.f, fmaxf(-40.f, acc[i][0] * scale)));
        v.y = __expf(fminf(40.f, fmaxf(-40.f, acc[i][1] * scale)));
        v.z = __expf(fminf(40.f, fmaxf(-40.f, acc[i][2] * scale)));
        v.w = __expf(fminf(40.f, fmaxf(-40.f, acc[i][3] * scale)));
        *(float4*)&C[(size_t)(m0 + ty * 8 + i) * NS + n0 + tx * 4] = v;
    }
}

// ---------------- heavy: mma.sync tf32 + ldmatrix (best R13 variant) ----------------
#define BPCH 260
#define APCH 132
#define B_OFF 0
#define A_OFF 133120
#define RED_OFF 200704
#define V2_OFF 201728
#define SMEM_SZ 202752

#define HALF_LOOP(AOFS, BOFS)                                                         \
    {                                                                                 \
        uint32_t fa[2][8], fb[2][8];                                                  \
        ldsm_x4(fa[0][0], fa[0][1], fa[0][2], fa[0][3], aBase + (AOFS));              \
        ldsm_x4(fa[0][4], fa[0][5], fa[0][6], fa[0][7], aBase + (AOFS) + 8448);       \
        ldsm_x4(fb[0][0], fb[0][1], fb[0][2], fb[0][3], bBase + (BOFS));              \
        ldsm_x4(fb[0][4], fb[0][5], fb[0][6], fb[0][7], bBase + (BOFS) + 16640);      \
        _Pragma("unroll")                                                             \
        for (int ks = 0; ks < 16; ks++) {                                             \
            const int cur = ks & 1, nxt = cur ^ 1;                                    \
            if (ks < 15) {                                                            \
                uint32_t ko = (uint32_t)((ks + 1) * 32);                              \
                ldsm_x4(fa[nxt][0], fa[nxt][1], fa[nxt][2], fa[nxt][3],               \
                        aBase + (AOFS) + ko);                                         \
                ldsm_x4(fa[nxt][4], fa[nxt][5], fa[nxt][6], fa[nxt][7],               \
                        aBase + (AOFS) + 8448 + ko);                                  \
                ldsm_x4(fb[nxt][0], fb[nxt][1], fb[nxt][2], fb[nxt][3],               \
                        bBase + (BOFS) + ko);                                         \
                ldsm_x4(fb[nxt][4], fb[nxt][5], fb[nxt][6], fb[nxt][7],               \
                        bBase + (BOFS) + 16640 + ko);                                 \
            }                                                                         \
            mma_tf32(acc[0][0], fa[cur][0], fa[cur][1], fa[cur][2], fa[cur][3],       \
                     fb[cur][0], fb[cur][1]);                                         \
            mma_tf32(acc[0][1], fa[cur][0], fa[cur][1], fa[cur][2], fa[cur][3],       \
                     fb[cur][2], fb[cur][3]);                                         \
            mma_tf32(acc[0][2], fa[cur][0], fa[cur][1], fa[cur][2], fa[cur][3],       \
                     fb[cur][4], fb[cur][5]);                                         \
            mma_tf32(acc[0][3], fa[cur][0], fa[cur][1], fa[cur][2], fa[cur][3],       \
                     fb[cur][6], fb[cur][7]);                                         \
            mma_tf32(acc[1][0], fa[cur][4], fa[cur][5], fa[cur][6], fa[cur][7],       \
                     fb[cur][0], fb[cur][1]);                                         \
            mma_tf32(acc[1][1], fa[cur][4], fa[cur][5], fa[cur][6], fa[cur][7],       \
                     fb[cur][2], fb[cur][3]);                                         \
            mma_tf32(acc[1][2], fa[cur][4], fa[cur][5], fa[cur][6], fa[cur][7],       \
                     fb[cur][4], fb[cur][5]);                                         \
            mma_tf32(acc[1][3], fa[cur][4], fa[cur][5], fa[cur][6], fa[cur][7],       \
                     fb[cur][6], fb[cur][7]);                                         \
        }                                                                             \
    }

__global__ void __launch_bounds__(256, 1) heavy_mma() {
    extern __shared__ __align__(16) char smem[];
    const uint32_t sb = smem_u32(smem);
    uint32_t* Bu  = (uint32_t*)(smem + B_OFF);
    uint32_t* Au  = (uint32_t*)(smem + A_OFF);
    float*    red = (float*)(smem + RED_OFF);
    float*    v2s = (float*)(smem + V2_OFF);

    int t = threadIdx.x, lane = t & 31, wid = t >> 5;
    int wi = wid >> 2, wj = wid & 3;            // 2(i) x 4(j)
    int i0 = wi * 32, j0 = wj * 32;
    int dg = blockIdx.x;                        // 0..4, 13 channels each
    int ib = blockIdx.y >> 1, jb = blockIdx.y & 1;
    int bh = blockIdx.z;

    const float* e2p = g_e2 + (size_t)bh * 65536 + (size_t)(ib * 64) * 256;
    const float* e3p = g_e3 + (size_t)bh * 65536 + (size_t)(jb * 128) * 256;
    const float* e1p = g_e1 + (size_t)bh * 65536 + (size_t)(ib * 64) * 256 + jb * 128;
    const float* v1b = g_v1t + (size_t)bh * DH * NS;
    const float* v2b = g_v2t + (size_t)bh * DH * NS;

    // ---- B static: tf32(e3) [128 x 256] pitch 260, built once ----
    for (int idx = t; idx < 8192; idx += 256) {   // 128 rows x 64 float4
        int r = idx >> 6, q = (idx & 63) << 2;
        float4 b = *(const float4*)&e3p[r * 256 + q];
        uint4 u;
        u.x = cvt_tf32(b.x); u.y = cvt_tf32(b.y);
        u.z = cvt_tf32(b.z); u.w = cvt_tf32(b.w);
        *(uint4*)&Bu[r * BPCH + q] = u;
    }

    // ---- raw e2 tile -> registers (once) ----
    float4 st0[8], st1[8];
#pragma unroll
    for (int q = 0; q < 8; q++) {
        int row = wid + 8 * q;
        st0[q] = *(const float4*)&e2p[row * 256 + lane * 4];
        st1[q] = *(const float4*)&e2p[row * 256 + 128 + lane * 4];
    }

    // ---- e1 fragments in registers (d-independent) ----
    float er[2][4][4];
#pragma unroll
    for (int mt = 0; mt < 2; mt++) {
        int ir = i0 + mt * 16 + (lane >> 2);
#pragma unroll
        for (int nt = 0; nt < 4; nt++) {
            int j = j0 + nt * 8 + (lane & 3) * 2;
            float2 w0 = *(const float2*)&e1p[(size_t)ir * 256 + j];
            float2 w1 = *(const float2*)&e1p[(size_t)(ir + 8) * 256 + j];
            er[mt][nt][0] = w0.x; er[mt][nt][1] = w0.y;
            er[mt][nt][2] = w1.x; er[mt][nt][3] = w1.y;
        }
    }

    // ---- v2 smem + v1 regs for channel 0 ----
    int d0 = dg * 13;
    v2s[t] = v2b[(size_t)d0 * NS + t];
    float vr0[4], vr1[4];
#pragma unroll
    for (int nt = 0; nt < 4; nt++) {
        int jg = jb * 128 + j0 + nt * 8 + (lane & 3) * 2;
        vr0[nt] = v1b[(size_t)d0 * NS + jg];
        vr1[nt] = v1b[(size_t)d0 * NS + jg + 1];
    }

    // ---- ldmatrix lane addresses ----
    int lr = lane & 7;
    uint32_t aRow = (uint32_t)(i0 + ((lane >> 3) & 1) * 8 + lr);
    uint32_t aK   = (uint32_t)((lane >> 4) * 4);
    uint32_t aBase = sb + A_OFF + (aRow * APCH + aK) * 4;  // +half*33792 +mt*8448 +ks*32
    uint32_t bRow = (uint32_t)(j0 + ((lane >> 4) & 1) * 8 + lr);
    uint32_t bK   = (uint32_t)(((lane >> 3) & 1) * 4);
    uint32_t bBase = sb + B_OFF + (bRow * BPCH + bK) * 4;  // +ntp*16640 +half*512 +ks*32

    __syncthreads();   // B + v2s ready

    float acc[2][4][4];

#pragma unroll 1
    for (int ch = 0; ch < 13; ch++) {
        int d = dg * 13 + ch;

        // ===== half 0: build A = tf32(e2*v2) into buf0 =====
#pragma unroll
        for (int q = 0; q < 8; q++) {
            int row = wid + 8 * q;
            float4 a = st0[q];
            float4 w = *(const float4*)&v2s[lane * 4];
            uint4 u;
            u.x = cvt_tf32(a.x * w.x); u.y = cvt_tf32(a.y * w.y);
            u.z = cvt_tf32(a.z * w.z); u.w = cvt_tf32(a.w * w.w);
            *(uint4*)&Au[row * APCH + lane * 4] = u;
        }
        __syncthreads();

#pragma unroll
        for (int m = 0; m < 2; m++)
#pragma unroll
            for (int n = 0; n < 4; n++)
#pragma unroll
                for (int c = 0; c < 4; c++) acc[m][n][c] = 0.f;

        HALF_LOOP(0u, 0u)

        // ===== half 1: build A into buf1 =====
#pragma unroll
        for (int q = 0; q < 8; q++) {
            int row = wid + 8 * q;
            float4 a = st1[q];
            float4 w = *(const float4*)&v2s[128 + lane * 4];
            uint4 u;
            u.x = cvt_tf32(a.x * w.x); u.y = cvt_tf32(a.y * w.y);
            u.z = cvt_tf32(a.z * w.z); u.w = cvt_tf32(a.w * w.w);
            *(uint4*)&Au[(64 + row) * APCH + lane * 4] = u;
        }
        __syncthreads();

        HALF_LOOP(33792u, 512u)

        // ===== epilogue: partial[i] = sum_j e1*v1*G =====
#pragma unroll
        for (int mt = 0; mt < 2; mt++) {
            float p0 = 0.f, p1 = 0.f;
#pragma unroll
            for (int nt = 0; nt < 4; nt++) {
                p0 += acc[mt][nt][0] * er[mt][nt][0] * vr0[nt]
                    + acc[mt][nt][1] * er[mt][nt][1] * vr1[nt];
                p1 += acc[mt][nt][2] * er[mt][nt][2] * vr0[nt]
                    + acc[mt][nt][3] * er[mt][nt][3] * vr1[nt];
            }
            p0 += __shfl_xor_sync(0xffffffffu, p0, 1);
            p0 += __shfl_xor_sync(0xffffffffu, p0, 2);
            p1 += __shfl_xor_sync(0xffffffffu, p1, 1);
            p1 += __shfl_xor_sync(0xffffffffu, p1, 2);
            if ((lane & 3) == 0) {
                int il = i0 + mt * 16 + (lane >> 2);
                red[il * 4 + wj] = p0;
                red[(il + 8) * 4 + wj] = p1;
            }
        }
        __syncthreads();

        // final store + stage next channel's v1/v2
        if (t < 64) {
            float s = red[t * 4] + red[t * 4 + 1] + red[t * 4 + 2] + red[t * 4 + 3];
            int ig = ib * 64 + t;
            if (d < 64) g_numP[jb][((size_t)bh * NS + ig) * DH + d] = s;
            else        g_denP[jb][(size_t)bh * NS + ig] = s;
        }
        int d2 = d + 1;
        v2s[t] = (d2 < 64) ? v2b[(size_t)d2 * NS + t] : 1.f;
#pragma unroll
        for (int nt = 0; nt < 4; nt++) {
            int jg = jb * 128 + j0 + nt * 8 + (lane & 3) * 2;
            vr0[nt] = (d2 < 64) ? v1b[(size_t)d2 * NS + jg] : 1.f;
            vr1[nt] = (d2 < 64) ? v1b[(size_t)d2 * NS + jg + 1] : 1.f;
        }
        __syncthreads();
    }
}

// ---------------- normalize: combine 2 jb partials, o = num/den ----------------
__global__ void normalize_kernel() {
    int idx = blockIdx.x * 256 + threadIdx.x;   // 0..262143
    int dd = idx & 63;
    int i  = (idx >> 6) & 255;
    int bh = idx >> 14;
    int b = bh >> 3, h = bh & 7;
    float num = g_numP[0][idx] + g_numP[1][idx];
    float den = g_denP[0][bh * NS + i] + g_denP[1][bh * NS + i];
    g_o[(size_t)(b * 256 + i) * 512 + h * 64 + dd] = num / den;
}

extern "C" void kernel_launch(void* const* d_in, const int* in_sizes, int n_in,
                              void* d_out, int out_size) {
    const float* x     = (const float*)d_in[0];
    const float* w_qkv = (const float*)d_in[1];
    const float* w_out = (const float*)d_in[2];
    const float* qw    = (const float*)d_in[3];
    const float* k1w   = (const float*)d_in[4];
    const float* k2w   = (const float*)d_in[5];
    float* out = (float*)d_out;

    float *qkv_p = nullptr, *o_p = nullptr;
    cudaGetSymbolAddress((void**)&qkv_p, g_qkv);
    cudaGetSymbolAddress((void**)&o_p, g_o);

    cudaFuncSetAttribute(heavy_mma, cudaFuncAttributeMaxDynamicSharedMemorySize, SMEM_SZ);

    // 1) qkv = x @ w_qkv   [512,512]@[512,2560], 64x64 tiles -> 320 CTAs
    sgemm64x64<<<dim3(40, 8), 256>>>(x, w_qkv, qkv_p, 512, 2560, 512);
    // 2) split + rmsnorm + pack (warp per row)
    pack_norm<<<512, 256>>>(qw, k1w, k2w);
    // 3) e1/e2/e3
    sims_kernel<<<dim3(4, 2, 48), 256>>>();
    // 4) heavy: 5 dgroups x (ib 4 x jb 2) x bh 16 = 640 CTAs
    heavy_mma<<<dim3(5, 8, 16), 256, SMEM_SZ>>>();
    // 5) normalize (sum 2 jb partials)
    normalize_kernel<<<1024, 256>>>();
    // 6) out = o @ w_out   [512,512]@[512,512], 64x64 tiles -> 64 CTAs
    sgemm64x64<<<dim3(8, 8), 256>>>(o_p, w_out, out, 512, 512, 512);
}

// round 16
// speedup vs baseline: 1.5940x; 1.4114x over previous
#include <cuda_runtime.h>
#include <cuda_fp16.h>
#include <cstdint>

#define BH 16
#define NS 256
#define DH 64
#define EPSF 1.1920929e-07f

// ---------------- scratch (device globals; no allocs) ----------------
__device__ __align__(16) float g_qkv[512 * 2560];
__device__ __align__(16) float g_qn [BH * NS * DH];
__device__ __align__(16) float g_k1 [BH * NS * DH];
__device__ __align__(16) float g_k2 [BH * NS * DH];
__device__ __align__(16) float g_v1t[BH * DH * NS];
__device__ __align__(16) float g_v2t[BH * DH * NS];
__device__ __align__(16) float g_e1 [BH * NS * NS];
__device__ __align__(16) float g_e2 [BH * NS * NS];
__device__ __align__(16) float g_e3 [BH * NS * NS];
__device__ __align__(16) float g_numP[2][BH * NS * DH];
__device__ __align__(16) float g_denP[2][BH * NS];
__device__ __align__(16) float g_o  [512 * 512];

__device__ __forceinline__ uint32_t smem_u32(const void* p) {
    uint32_t a;
    asm("{ .reg .u64 t; cvta.to.shared.u64 t, %1; cvt.u32.u64 %0, t; }" : "=r"(a) : "l"(p));
    return a;
}
// pack two floats into f16x2 (lo = first arg, hi = second)
__device__ __forceinline__ uint32_t cvt_h2(float lo, float hi) {
    uint32_t r; asm("cvt.rn.f16x2.f32 %0, %1, %2;" : "=r"(r) : "f"(hi), "f"(lo)); return r;
}
__device__ __forceinline__ void mma_f16(float* c, const uint32_t* a,
                                        uint32_t b0, uint32_t b1) {
    asm volatile("mma.sync.aligned.m16n8k16.row.col.f32.f16.f16.f32 "
        "{%0,%1,%2,%3}, {%4,%5,%6,%7}, {%8,%9}, {%0,%1,%2,%3};"
        : "+f"(c[0]), "+f"(c[1]), "+f"(c[2]), "+f"(c[3])
        : "r"(a[0]), "r"(a[1]), "r"(a[2]), "r"(a[3]), "r"(b0), "r"(b1));
}
__device__ __forceinline__ void ldsm_x4(uint32_t& r0, uint32_t& r1,
                                        uint32_t& r2, uint32_t& r3, uint32_t a) {
    asm volatile("ldmatrix.sync.aligned.m8n8.x4.shared.b16 {%0,%1,%2,%3}, [%4];"
                 : "=r"(r0), "=r"(r1), "=r"(r2), "=r"(r3) : "r"(a));
}

// ---------------- SGEMM 64x64 tiles: C[M,N] = A[M,K] @ B[K,N] ----------------
__global__ void sgemm64x64(const float* __restrict__ A, const float* __restrict__ B,
                           float* __restrict__ C, int M, int N, int K) {
    __shared__ float As[16][64];
    __shared__ float Bs[16][64];
    int t = threadIdx.x;
    int tx = t & 15, ty = t >> 4;
    int m0 = blockIdx.y * 64, n0 = blockIdx.x * 64;

    float acc[4][4];
#pragma unroll
    for (int i = 0; i < 4; i++)
#pragma unroll
        for (int j = 0; j < 4; j++) acc[i][j] = 0.f;

    for (int kt = 0; kt < K; kt += 16) {
        {
            int m = t & 63, kq = t >> 6;
            float4 v = *(const float4*)&A[(size_t)(m0 + m) * K + kt + kq * 4];
            As[kq * 4 + 0][m] = v.x; As[kq * 4 + 1][m] = v.y;
            As[kq * 4 + 2][m] = v.z; As[kq * 4 + 3][m] = v.w;
        }
        {
            int kk = t >> 4, nq = t & 15;
            float4 v = *(const float4*)&B[(size_t)(kt + kk) * N + n0 + nq * 4];
            *(float4*)&Bs[kk][nq * 4] = v;
        }
        __syncthreads();
#pragma unroll
        for (int kk = 0; kk < 16; kk++) {
            float4 b = *(float4*)&Bs[kk][tx * 4];
            float a[4];
#pragma unroll
            for (int i = 0; i < 4; i++) a[i] = As[kk][ty * 4 + i];
#pragma unroll
            for (int i = 0; i < 4; i++) {
                acc[i][0] += a[i] * b.x; acc[i][1] += a[i] * b.y;
                acc[i][2] += a[i] * b.z; acc[i][3] += a[i] * b.w;
            }
        }
        __syncthreads();
    }
#pragma unroll
    for (int i = 0; i < 4; i++) {
        float4 v = make_float4(acc[i][0], acc[i][1], acc[i][2], acc[i][3]);
        *(float4*)&C[(size_t)(m0 + ty * 4 + i) * N + n0 + tx * 4] = v;
    }
}

// ---------------- split + rmsnorm + pack: warp per (bh,n) row ----------------
__global__ void pack_norm(const float* __restrict__ qw,
                          const float* __restrict__ k1w,
                          const float* __restrict__ k2w) {
    int row = blockIdx.x * 8 + (threadIdx.x >> 5);
    int lane = threadIdx.x & 31;
    int bh = row >> 8, n = row & 255;
    int b = bh >> 3, h = bh & 7;
    size_t base = (size_t)(b * 256 + n) * 2560 + h * 64;

    float q0  = g_qkv[base + lane],        q1  = g_qkv[base + lane + 32];
    float k10 = g_qkv[base + 512 + lane],  k11 = g_qkv[base + 512 + lane + 32];
    float k20 = g_qkv[base + 1024 + lane], k21 = g_qkv[base + 1024 + lane + 32];
    float v10 = g_qkv[base + 1536 + lane], v11 = g_qkv[base + 1536 + lane + 32];
    float v20 = g_qkv[base + 2048 + lane], v21 = g_qkv[base + 2048 + lane + 32];

    float sq = q0 * q0 + q1 * q1;
    float s1 = k10 * k10 + k11 * k11;
    float s2 = k20 * k20 + k21 * k21;
#pragma unroll
    for (int o = 16; o; o >>= 1) {
        sq += __shfl_xor_sync(0xffffffffu, sq, o);
        s1 += __shfl_xor_sync(0xffffffffu, s1, o);
        s2 += __shfl_xor_sync(0xffffffffu, s2, o);
    }
    float rq = rsqrtf(sq * (1.f / 64.f) + EPSF);
    float r1 = rsqrtf(s1 * (1.f / 64.f) + EPSF);
    float r2 = rsqrtf(s2 * (1.f / 64.f) + EPSF);

    int rb = bh * NS * DH + n * DH;
    g_qn[rb + lane]      = q0 * rq * qw[lane] * 0.125f;
    g_qn[rb + lane + 32] = q1 * rq * qw[lane + 32] * 0.125f;
    g_k1[rb + lane]      = k10 * r1 * k1w[lane];
    g_k1[rb + lane + 32] = k11 * r1 * k1w[lane + 32];
    g_k2[rb + lane]      = k20 * r2 * k2w[lane];
    g_k2[rb + lane + 32] = k21 * r2 * k2w[lane + 32];
    int vb = bh * DH * NS + n;
    g_v1t[vb + lane * NS]        = v10;
    g_v1t[vb + (lane + 32) * NS] = v11;
    g_v2t[vb + lane * NS]        = v20;
    g_v2t[vb + (lane + 32) * NS] = v21;
}

// ---------------- sims: e = exp(clip(scale * L @ R^T)) ----------------
__global__ void sims_kernel() {
    int z = blockIdx.z;
    int bh = z / 3, mat = z % 3;
    const float* L = ((mat == 2) ? g_k1 : g_qn) + bh * NS * DH;
    const float* R = ((mat == 0) ? g_k1 : g_k2) + bh * NS * DH;
    float* C = ((mat == 0) ? g_e1 : (mat == 1) ? g_e2 : g_e3) + (size_t)bh * NS * NS;
    float scale = (mat == 2) ? 0.125f : 1.f;

    __shared__ float As[16][128];
    __shared__ float Bs[16][64];
    int t = threadIdx.x, tx = t & 15, ty = t >> 4;
    int m0 = blockIdx.y * 128, n0 = blockIdx.x * 64;

    float acc[8][4];
#pragma unroll
    for (int i = 0; i < 8; i++)
#pragma unroll
        for (int j = 0; j < 4; j++) acc[i][j] = 0.f;

    for (int kt = 0; kt < 64; kt += 16) {
#pragma unroll
        for (int q = 0; q < 2; q++) {
            int lin = t + q * 256;
            int m = lin & 127, kq = lin >> 7;
            float4 v = *(const float4*)&L[(m0 + m) * 64 + kt + kq * 4];
            As[kq * 4 + 0][m] = v.x; As[kq * 4 + 1][m] = v.y;
            As[kq * 4 + 2][m] = v.z; As[kq * 4 + 3][m] = v.w;
        }
        {
            int n = t & 63, kq = t >> 6;
            float4 v = *(const float4*)&R[(n0 + n) * 64 + kt + kq * 4];
            Bs[kq * 4 + 0][n] = v.x; Bs[kq * 4 + 1][n] = v.y;
            Bs[kq * 4 + 2][n] = v.z; Bs[kq * 4 + 3][n] = v.w;
        }
        __syncthreads();
#pragma unroll
        for (int kk = 0; kk < 16; kk++) {
            float4 b = *(float4*)&Bs[kk][tx * 4];
            float a[8];
#pragma unroll
            for (int i = 0; i < 8; i++) a[i] = As[kk][ty * 8 + i];
#pragma unroll
            for (int i = 0; i < 8; i++) {
                acc[i][0] += a[i] * b.x; acc[i][1] += a[i] * b.y;
                acc[i][2] += a[i] * b.z; acc[i][3] += a[i] * b.w;
            }
        }
        __syncthreads();
    }
#pragma unroll
    for (int i = 0; i < 8; i++) {
        float4 v;
        v.x = __expf(fminf(40.f, fmaxf(-40.f, acc[i][0] * scale)));
        v.y = __expf(fminf(40.f, fmaxf(-40.f, acc[i][1] * scale)));
        v.z = __expf(fminf(40.f, fmaxf(-40.f, acc[i][2] * scale)));
        v.w = __expf(fminf(40.f, fmaxf(-40.f, acc[i][3] * scale)));
        *(float4*)&C[(size_t)(m0 + ty * 8 + i) * NS + n0 + tx * 4] = v;
    }
}

// ---------------- heavy: mma.sync fp16 (m16n8k16) + ldmatrix ----------------
// CTA (dg, ib, jb, bh): tile 64(i) x 128(j), 256 threads, 8 warps,
// warp grid 2(i) x 4(j), warp tile 32x32.
//   G[i,j] = sum_k (e2[i,k]*v2[k,d]) * e3[j,k]
// fp16 operands (|sim| <= 8 by Cauchy-Schwarz => e <= e^8: no overflow);
// fp16 mantissa == tf32 mantissa (11 bits) => same precision as tf32 path.
// B = fp16(e3) [128 x 256 halves] built once; A = fp16(e2*v2_d) rebuilt per
// channel from register-resident raw e2. Pitch 264 halves (528 B == 16 mod
// 128) -> conflict-free ldmatrix.
#define HPCH 264
#define B_OFF 0
#define A_OFF 67584
#define RED_OFF 101376
#define V2_OFF 102400
#define SMEM_SZ 103424

__global__ void __launch_bounds__(256, 1) heavy_mma() {
    extern __shared__ __align__(16) char smem[];
    const uint32_t sb = smem_u32(smem);
    char*  Bb  = smem + B_OFF;
    char*  Ab  = smem + A_OFF;
    float* red = (float*)(smem + RED_OFF);
    float* v2s = (float*)(smem + V2_OFF);

    int t = threadIdx.x, lane = t & 31, wid = t >> 5;
    int wi = wid >> 2, wj = wid & 3;            // 2(i) x 4(j)
    int i0 = wi * 32, j0 = wj * 32;
    int dg = blockIdx.x;                        // 0..4, 13 channels each
    int ib = blockIdx.y >> 1, jb = blockIdx.y & 1;
    int bh = blockIdx.z;

    const float* e2p = g_e2 + (size_t)bh * 65536 + (size_t)(ib * 64) * 256;
    const float* e3p = g_e3 + (size_t)bh * 65536 + (size_t)(jb * 128) * 256;
    const float* e1p = g_e1 + (size_t)bh * 65536 + (size_t)(ib * 64) * 256 + jb * 128;
    const float* v1b = g_v1t + (size_t)bh * DH * NS;
    const float* v2b = g_v2t + (size_t)bh * DH * NS;

    // ---- B static: fp16(e3) [128 rows x 256 halves], built once ----
    for (int idx = t; idx < 8192; idx += 256) {   // 128 rows x 64 float4
        int r = idx >> 6, q4 = (idx & 63) << 2;
        float4 b = *(const float4*)&e3p[r * 256 + q4];
        uint2 u;
        u.x = cvt_h2(b.x, b.y);
        u.y = cvt_h2(b.z, b.w);
        *(uint2*)(Bb + r * (HPCH * 2) + q4 * 2) = u;
    }

    // ---- raw e2 tile -> registers (once) ----
    float4 st0[8], st1[8];
#pragma unroll
    for (int q = 0; q < 8; q++) {
        int row = wid + 8 * q;
        st0[q] = *(const float4*)&e2p[row * 256 + lane * 4];
        st1[q] = *(const float4*)&e2p[row * 256 + 128 + lane * 4];
    }

    // ---- e1 fragments in registers (d-independent) ----
    float er[2][4][4];
#pragma unroll
    for (int mt = 0; mt < 2; mt++) {
        int ir = i0 + mt * 16 + (lane >> 2);
#pragma unroll
        for (int nt = 0; nt < 4; nt++) {
            int j = j0 + nt * 8 + (lane & 3) * 2;
            float2 w0 = *(const float2*)&e1p[(size_t)ir * 256 + j];
            float2 w1 = *(const float2*)&e1p[(size_t)(ir + 8) * 256 + j];
            er[mt][nt][0] = w0.x; er[mt][nt][1] = w0.y;
            er[mt][nt][2] = w1.x; er[mt][nt][3] = w1.y;
        }
    }

    // ---- v2 smem + v1 regs for channel 0 ----
    int d0 = dg * 13;
    v2s[t] = v2b[(size_t)d0 * NS + t];
    float vr0[4], vr1[4];
#pragma unroll
    for (int nt = 0; nt < 4; nt++) {
        int jg = jb * 128 + j0 + nt * 8 + (lane & 3) * 2;
        vr0[nt] = v1b[(size_t)d0 * NS + jg];
        vr1[nt] = v1b[(size_t)d0 * NS + jg + 1];
    }

    // ---- ldmatrix lane addresses (fp16 m16n8k16 fragments) ----
    // A .x4: mats = [m0-7@k0],[m8-15@k0],[m0-7@k8h],[m8-15@k8h]
    int lr7 = lane & 7;
    uint32_t aRow = (uint32_t)(i0 + ((lane >> 3) & 1) * 8 + lr7);
    uint32_t aBase = sb + A_OFF + aRow * (HPCH * 2) + (uint32_t)(lane >> 4) * 16;
    // B .x4 (2 n-octets): mats = [n0-7@k0],[n0-7@k8h],[n8-15@k0],[n8-15@k8h]
    uint32_t bRow = (uint32_t)(j0 + ((lane >> 4) & 1) * 8 + lr7);
    uint32_t bBase = sb + B_OFF + bRow * (HPCH * 2) + (uint32_t)((lane >> 3) & 1) * 16;
    // per k16-step advance: +32 bytes; mt/npair stride: 16 rows = 8448 bytes

    __syncthreads();   // B + v2s ready

    float acc[2][4][4];

#pragma unroll 1
    for (int ch = 0; ch < 13; ch++) {
        int d = dg * 13 + ch;

        // ===== build full A = fp16(e2 * v2_d) [64 x 256 halves] =====
#pragma unroll
        for (int q = 0; q < 8; q++) {
            int row = wid + 8 * q;
            char* arow = Ab + row * (HPCH * 2);
            float4 a = st0[q];
            float4 w = *(const float4*)&v2s[lane * 4];
            uint2 u;
            u.x = cvt_h2(a.x * w.x, a.y * w.y);
            u.y = cvt_h2(a.z * w.z, a.w * w.w);
            *(uint2*)(arow + lane * 8) = u;
            a = st1[q];
            w = *(const float4*)&v2s[128 + lane * 4];
            u.x = cvt_h2(a.x * w.x, a.y * w.y);
            u.y = cvt_h2(a.z * w.z, a.w * w.w);
            *(uint2*)(arow + 256 + lane * 8) = u;
        }
        __syncthreads();

#pragma unroll
        for (int m = 0; m < 2; m++)
#pragma unroll
            for (int n = 0; n < 4; n++)
#pragma unroll
                for (int c = 0; c < 4; c++) acc[m][n][c] = 0.f;

        // ===== mainloop: 16 k16-steps, 4 LDSM.x4 + 8 MMA each =====
#pragma unroll
        for (int ks = 0; ks < 16; ks++) {
            uint32_t ko = (uint32_t)(ks * 32);
            uint32_t a0[4], a1[4], b0[4], b1[4];
            ldsm_x4(a0[0], a0[1], a0[2], a0[3], aBase + ko);
            ldsm_x4(a1[0], a1[1], a1[2], a1[3], aBase + 8448 + ko);
            ldsm_x4(b0[0], b0[1], b0[2], b0[3], bBase + ko);
            ldsm_x4(b1[0], b1[1], b1[2], b1[3], bBase + 8448 + ko);
            mma_f16(acc[0][0], a0, b0[0], b0[1]);
            mma_f16(acc[0][1], a0, b0[2], b0[3]);
            mma_f16(acc[0][2], a0, b1[0], b1[1]);
            mma_f16(acc[0][3], a0, b1[2], b1[3]);
            mma_f16(acc[1][0], a1, b0[0], b0[1]);
            mma_f16(acc[1][1], a1, b0[2], b0[3]);
            mma_f16(acc[1][2], a1, b1[0], b1[1]);
            mma_f16(acc[1][3], a1, b1[2], b1[3]);
        }

        // ===== epilogue: partial[i] = sum_j e1*v1*G =====
#pragma unroll
        for (int mt = 0; mt < 2; mt++) {
            float p0 = 0.f, p1 = 0.f;
#pragma unroll
            for (int nt = 0; nt < 4; nt++) {
                p0 += acc[mt][nt][0] * er[mt][nt][0] * vr0[nt]
                    + acc[mt][nt][1] * er[mt][nt][1] * vr1[nt];
                p1 += acc[mt][nt][2] * er[mt][nt][2] * vr0[nt]
                    + acc[mt][nt][3] * er[mt][nt][3] * vr1[nt];
            }
            p0 += __shfl_xor_sync(0xffffffffu, p0, 1);
            p0 += __shfl_xor_sync(0xffffffffu, p0, 2);
            p1 += __shfl_xor_sync(0xffffffffu, p1, 1);
            p1 += __shfl_xor_sync(0xffffffffu, p1, 2);
            if ((lane & 3) == 0) {
                int il = i0 + mt * 16 + (lane >> 2);
                red[il * 4 + wj] = p0;
                red[(il + 8) * 4 + wj] = p1;
            }
        }
        __syncthreads();   // also guarantees all warps done reading A

        // final store + stage next channel's v1/v2
        if (t < 64) {
            float s = red[t * 4] + red[t * 4 + 1] + red[t * 4 + 2] + red[t * 4 + 3];
            int ig = ib * 64 + t;
            if (d < 64) g_numP[jb][((size_t)bh * NS + ig) * DH + d] = s;
            else        g_denP[jb][(size_t)bh * NS + ig] = s;
        }
        int d2 = d + 1;
        v2s[t] = (d2 < 64) ? v2b[(size_t)d2 * NS + t] : 1.f;
#pragma unroll
        for (int nt = 0; nt < 4; nt++) {
            int jg = jb * 128 + j0 + nt * 8 + (lane & 3) * 2;
            vr0[nt] = (d2 < 64) ? v1b[(size_t)d2 * NS + jg] : 1.f;
            vr1[nt] = (d2 < 64) ? v1b[(size_t)d2 * NS + jg + 1] : 1.f;
        }
        __syncthreads();
    }
}

// ---------------- normalize: combine 2 jb partials, o = num/den ----------------
__global__ void normalize_kernel() {
    int idx = blockIdx.x * 256 + threadIdx.x;
    int dd = idx & 63;
    int i  = (idx >> 6) & 255;
    int bh = idx >> 14;
    int b = bh >> 3, h = bh & 7;
    float num = g_numP[0][idx] + g_numP[1][idx];
    float den = g_denP[0][bh * NS + i] + g_denP[1][bh * NS + i];
    g_o[(size_t)(b * 256 + i) * 512 + h * 64 + dd] = num / den;
}

extern "C" void kernel_launch(void* const* d_in, const int* in_sizes, int n_in,
                              void* d_out, int out_size) {
    const float* x     = (const float*)d_in[0];
    const float* w_qkv = (const float*)d_in[1];
    const float* w_out = (const float*)d_in[2];
    const float* qw    = (const float*)d_in[3];
    const float* k1w   = (const float*)d_in[4];
    const float* k2w   = (const float*)d_in[5];
    float* out = (float*)d_out;

    float *qkv_p = nullptr, *o_p = nullptr;
    cudaGetSymbolAddress((void**)&qkv_p, g_qkv);
    cudaGetSymbolAddress((void**)&o_p, g_o);

    cudaFuncSetAttribute(heavy_mma, cudaFuncAttributeMaxDynamicSharedMemorySize, SMEM_SZ);

    // 1) qkv = x @ w_qkv   [512,512]@[512,2560], 64x64 tiles -> 320 CTAs
    sgemm64x64<<<dim3(40, 8), 256>>>(x, w_qkv, qkv_p, 512, 2560, 512);
    // 2) split + rmsnorm + pack (warp per row)
    pack_norm<<<512, 256>>>(qw, k1w, k2w);
    // 3) e1/e2/e3
    sims_kernel<<<dim3(4, 2, 48), 256>>>();
    // 4) heavy: 5 dgroups x (ib 4 x jb 2) x bh 16 = 640 CTAs, fp16 MMA
    heavy_mma<<<dim3(5, 8, 16), 256, SMEM_SZ>>>();
    // 5) normalize (sum 2 jb partials)
    normalize_kernel<<<1024, 256>>>();
    // 6) out = o @ w_out   [512,512]@[512,512], 64x64 tiles -> 64 CTAs
    sgemm64x64<<<dim3(8, 8), 256>>>(o_p, w_out, out, 512, 512, 512);
}

// round 17
// speedup vs baseline: 1.7620x; 1.1054x over previous
#include <cuda_runtime.h>
#include <cuda_fp16.h>
#include <cstdint>

#define BH 16
#define NS 256
#define DH 64
#define EPSF 1.1920929e-07f

// ---------------- scratch (device globals; no allocs) ----------------
__device__ __align__(16) float g_qkv[512 * 2560];
__device__ __align__(16) float g_qn [BH * NS * DH];
__device__ __align__(16) float g_k1 [BH * NS * DH];
__device__ __align__(16) float g_k2 [BH * NS * DH];
__device__ __align__(16) float g_v1t[BH * DH * NS];
__device__ __align__(16) float g_v2t[BH * DH * NS];
__device__ __align__(16) float g_e1 [BH * NS * NS];
__device__ __align__(16) float g_e2 [BH * NS * NS];
__device__ __align__(16) float g_e3 [BH * NS * NS];
__device__ __align__(16) float g_numP[2][BH * NS * DH];
__device__ __align__(16) float g_denP[2][BH * NS];
__device__ __align__(16) float g_o  [512 * 512];

__device__ __forceinline__ uint32_t smem_u32(const void* p) {
    uint32_t a;
    asm("{ .reg .u64 t; cvta.to.shared.u64 t, %1; cvt.u32.u64 %0, t; }" : "=r"(a) : "l"(p));
    return a;
}
// pack two floats into f16x2 (lo = first arg, hi = second)
__device__ __forceinline__ uint32_t cvt_h2(float lo, float hi) {
    uint32_t r; asm("cvt.rn.f16x2.f32 %0, %1, %2;" : "=r"(r) : "f"(hi), "f"(lo)); return r;
}
__device__ __forceinline__ uint32_t hmul2u(uint32_t a, uint32_t b) {
    uint32_t r; asm("mul.f16x2 %0, %1, %2;" : "=r"(r) : "r"(a), "r"(b)); return r;
}
__device__ __forceinline__ void mma_f16(float* c, const uint32_t* a,
                                        uint32_t b0, uint32_t b1) {
    asm volatile("mma.sync.aligned.m16n8k16.row.col.f32.f16.f16.f32 "
        "{%0,%1,%2,%3}, {%4,%5,%6,%7}, {%8,%9}, {%0,%1,%2,%3};"
        : "+f"(c[0]), "+f"(c[1]), "+f"(c[2]), "+f"(c[3])
        : "r"(a[0]), "r"(a[1]), "r"(a[2]), "r"(a[3]), "r"(b0), "r"(b1));
}
__device__ __forceinline__ void ldsm_x4(uint32_t& r0, uint32_t& r1,
                                        uint32_t& r2, uint32_t& r3, uint32_t a) {
    asm volatile("ldmatrix.sync.aligned.m8n8.x4.shared.b16 {%0,%1,%2,%3}, [%4];"
                 : "=r"(r0), "=r"(r1), "=r"(r2), "=r"(r3) : "r"(a));
}

// ---------------- SGEMM 64x64 tiles: C[M,N] = A[M,K] @ B[K,N] ----------------
__global__ void sgemm64x64(const float* __restrict__ A, const float* __restrict__ B,
                           float* __restrict__ C, int M, int N, int K) {
    __shared__ float As[16][64];
    __shared__ float Bs[16][64];
    int t = threadIdx.x;
    int tx = t & 15, ty = t >> 4;
    int m0 = blockIdx.y * 64, n0 = blockIdx.x * 64;

    float acc[4][4];
#pragma unroll
    for (int i = 0; i < 4; i++)
#pragma unroll
        for (int j = 0; j < 4; j++) acc[i][j] = 0.f;

    for (int kt = 0; kt < K; kt += 16) {
        {
            int m = t & 63, kq = t >> 6;
            float4 v = *(const float4*)&A[(size_t)(m0 + m) * K + kt + kq * 4];
            As[kq * 4 + 0][m] = v.x; As[kq * 4 + 1][m] = v.y;
            As[kq * 4 + 2][m] = v.z; As[kq * 4 + 3][m] = v.w;
        }
        {
            int kk = t >> 4, nq = t & 15;
            float4 v = *(const float4*)&B[(size_t)(kt + kk) * N + n0 + nq * 4];
            *(float4*)&Bs[kk][nq * 4] = v;
        }
        __syncthreads();
#pragma unroll
        for (int kk = 0; kk < 16; kk++) {
            float4 b = *(float4*)&Bs[kk][tx * 4];
            float a[4];
#pragma unroll
            for (int i = 0; i < 4; i++) a[i] = As[kk][ty * 4 + i];
#pragma unroll
            for (int i = 0; i < 4; i++) {
                acc[i][0] += a[i] * b.x; acc[i][1] += a[i] * b.y;
                acc[i][2] += a[i] * b.z; acc[i][3] += a[i] * b.w;
            }
        }
        __syncthreads();
    }
#pragma unroll
    for (int i = 0; i < 4; i++) {
        float4 v = make_float4(acc[i][0], acc[i][1], acc[i][2], acc[i][3]);
        *(float4*)&C[(size_t)(m0 + ty * 4 + i) * N + n0 + tx * 4] = v;
    }
}

// ---------------- split + rmsnorm + pack: warp per (bh,n) row ----------------
__global__ void pack_norm(const float* __restrict__ qw,
                          const float* __restrict__ k1w,
                          const float* __restrict__ k2w) {
    int row = blockIdx.x * 8 + (threadIdx.x >> 5);
    int lane = threadIdx.x & 31;
    int bh = row >> 8, n = row & 255;
    int b = bh >> 3, h = bh & 7;
    size_t base = (size_t)(b * 256 + n) * 2560 + h * 64;

    float q0  = g_qkv[base + lane],        q1  = g_qkv[base + lane + 32];
    float k10 = g_qkv[base + 512 + lane],  k11 = g_qkv[base + 512 + lane + 32];
    float k20 = g_qkv[base + 1024 + lane], k21 = g_qkv[base + 1024 + lane + 32];
    float v10 = g_qkv[base + 1536 + lane], v11 = g_qkv[base + 1536 + lane + 32];
    float v20 = g_qkv[base + 2048 + lane], v21 = g_qkv[base + 2048 + lane + 32];

    float sq = q0 * q0 + q1 * q1;
    float s1 = k10 * k10 + k11 * k11;
    float s2 = k20 * k20 + k21 * k21;
#pragma unroll
    for (int o = 16; o; o >>= 1) {
        sq += __shfl_xor_sync(0xffffffffu, sq, o);
        s1 += __shfl_xor_sync(0xffffffffu, s1, o);
        s2 += __shfl_xor_sync(0xffffffffu, s2, o);
    }
    float rq = rsqrtf(sq * (1.f / 64.f) + EPSF);
    float r1 = rsqrtf(s1 * (1.f / 64.f) + EPSF);
    float r2 = rsqrtf(s2 * (1.f / 64.f) + EPSF);

    int rb = bh * NS * DH + n * DH;
    g_qn[rb + lane]      = q0 * rq * qw[lane] * 0.125f;
    g_qn[rb + lane + 32] = q1 * rq * qw[lane + 32] * 0.125f;
    g_k1[rb + lane]      = k10 * r1 * k1w[lane];
    g_k1[rb + lane + 32] = k11 * r1 * k1w[lane + 32];
    g_k2[rb + lane]      = k20 * r2 * k2w[lane];
    g_k2[rb + lane + 32] = k21 * r2 * k2w[lane + 32];
    int vb = bh * DH * NS + n;
    g_v1t[vb + lane * NS]        = v10;
    g_v1t[vb + (lane + 32) * NS] = v11;
    g_v2t[vb + lane * NS]        = v20;
    g_v2t[vb + (lane + 32) * NS] = v21;
}

// ---------------- sims: e = exp(clip(scale * L @ R^T)) ----------------
__global__ void sims_kernel() {
    int z = blockIdx.z;
    int bh = z / 3, mat = z % 3;
    const float* L = ((mat == 2) ? g_k1 : g_qn) + bh * NS * DH;
    const float* R = ((mat == 0) ? g_k1 : g_k2) + bh * NS * DH;
    float* C = ((mat == 0) ? g_e1 : (mat == 1) ? g_e2 : g_e3) + (size_t)bh * NS * NS;
    float scale = (mat == 2) ? 0.125f : 1.f;

    __shared__ float As[16][128];
    __shared__ float Bs[16][64];
    int t = threadIdx.x, tx = t & 15, ty = t >> 4;
    int m0 = blockIdx.y * 128, n0 = blockIdx.x * 64;

    float acc[8][4];
#pragma unroll
    for (int i = 0; i < 8; i++)
#pragma unroll
        for (int j = 0; j < 4; j++) acc[i][j] = 0.f;

    for (int kt = 0; kt < 64; kt += 16) {
#pragma unroll
        for (int q = 0; q < 2; q++) {
            int lin = t + q * 256;
            int m = lin & 127, kq = lin >> 7;
            float4 v = *(const float4*)&L[(m0 + m) * 64 + kt + kq * 4];
            As[kq * 4 + 0][m] = v.x; As[kq * 4 + 1][m] = v.y;
            As[kq * 4 + 2][m] = v.z; As[kq * 4 + 3][m] = v.w;
        }
        {
            int n = t & 63, kq = t >> 6;
            float4 v = *(const float4*)&R[(n0 + n) * 64 + kt + kq * 4];
            Bs[kq * 4 + 0][n] = v.x; Bs[kq * 4 + 1][n] = v.y;
            Bs[kq * 4 + 2][n] = v.z; Bs[kq * 4 + 3][n] = v.w;
        }
        __syncthreads();
#pragma unroll
        for (int kk = 0; kk < 16; kk++) {
            float4 b = *(float4*)&Bs[kk][tx * 4];
            float a[8];
#pragma unroll
            for (int i = 0; i < 8; i++) a[i] = As[kk][ty * 8 + i];
#pragma unroll
            for (int i = 0; i < 8; i++) {
                acc[i][0] += a[i] * b.x; acc[i][1] += a[i] * b.y;
                acc[i][2] += a[i] * b.z; acc[i][3] += a[i] * b.w;
            }
        }
        __syncthreads();
    }
#pragma unroll
    for (int i = 0; i < 8; i++) {
        float4 v;
        v.x = __expf(fminf(40.f, fmaxf(-40.f, acc[i][0] * scale)));
        v.y = __expf(fminf(40.f, fmaxf(-40.f, acc[i][1] * scale)));
        v.z = __expf(fminf(40.f, fmaxf(-40.f, acc[i][2] * scale)));
        v.w = __expf(fminf(40.f, fmaxf(-40.f, acc[i][3] * scale)));
        *(float4*)&C[(size_t)(m0 + ty * 8 + i) * NS + n0 + tx * 4] = v;
    }
}

// ---------------- heavy: fp16 mma, register-diet for 2 CTAs/SM ----------------
// CTA (dg, ib, jb, bh): tile 64(i) x 128(j), 256 threads, 8 warps,
// warp grid 2(i) x 4(j), warp tile 32x32. TWO CTAs per SM (128-reg cap via
// launch_bounds): one CTA's A-build/epilogue overlaps the other's MMA burst.
// Register diet: e2 staged as f16x2 (32 regs), e1 frags as f16x2 (16 regs),
// A-build = mul.f16x2 on packed operands.
#define HPCH 264
#define B_OFF 0
#define A_OFF 67584
#define RED_OFF 101376
#define V2_OFF 102400
#define SMEM_SZ 103424

__global__ void __launch_bounds__(256, 2) heavy_mma() {
    extern __shared__ __align__(16) char smem[];
    const uint32_t sb = smem_u32(smem);
    char*     Bb  = smem + B_OFF;
    char*     Ab  = smem + A_OFF;
    float*    red = (float*)(smem + RED_OFF);
    uint32_t* v2u = (uint32_t*)(smem + V2_OFF);   // 128 f16x2 pairs

    int t = threadIdx.x, lane = t & 31, wid = t >> 5;
    int wi = wid >> 2, wj = wid & 3;            // 2(i) x 4(j)
    int i0 = wi * 32, j0 = wj * 32;
    int dg = blockIdx.x;                        // 0..4, 13 channels each
    int ib = blockIdx.y >> 1, jb = blockIdx.y & 1;
    int bh = blockIdx.z;

    const float* e2p = g_e2 + (size_t)bh * 65536 + (size_t)(ib * 64) * 256;
    const float* e3p = g_e3 + (size_t)bh * 65536 + (size_t)(jb * 128) * 256;
    const float* e1p = g_e1 + (size_t)bh * 65536 + (size_t)(ib * 64) * 256 + jb * 128;
    const float* v1b = g_v1t + (size_t)bh * DH * NS;
    const float* v2b = g_v2t + (size_t)bh * DH * NS;

    // ---- B static: fp16(e3) [128 rows x 256 halves], built once ----
    for (int idx = t; idx < 8192; idx += 256) {   // 128 rows x 64 float4
        int r = idx >> 6, q4 = (idx & 63) << 2;
        float4 b = *(const float4*)&e3p[r * 256 + q4];
        uint2 u;
        u.x = cvt_h2(b.x, b.y);
        u.y = cvt_h2(b.z, b.w);
        *(uint2*)(Bb + r * (HPCH * 2) + q4 * 2) = u;
    }

    // ---- raw e2 tile -> f16x2 registers (once): 32 regs ----
    uint2 e2h0[8], e2h1[8];
#pragma unroll
    for (int q = 0; q < 8; q++) {
        int row = wid + 8 * q;
        float4 a = *(const float4*)&e2p[row * 256 + lane * 4];
        e2h0[q].x = cvt_h2(a.x, a.y);
        e2h0[q].y = cvt_h2(a.z, a.w);
        a = *(const float4*)&e2p[row * 256 + 128 + lane * 4];
        e2h1[q].x = cvt_h2(a.x, a.y);
        e2h1[q].y = cvt_h2(a.z, a.w);
    }

    // ---- e1 fragments as f16x2 (d-independent): 16 regs ----
    uint32_t er2[2][4][2];
#pragma unroll
    for (int mt = 0; mt < 2; mt++) {
        int ir = i0 + mt * 16 + (lane >> 2);
#pragma unroll
        for (int nt = 0; nt < 4; nt++) {
            int j = j0 + nt * 8 + (lane & 3) * 2;
            er2[mt][nt][0] = cvt_h2(e1p[(size_t)ir * 256 + j],
                                    e1p[(size_t)ir * 256 + j + 1]);
            er2[mt][nt][1] = cvt_h2(e1p[(size_t)(ir + 8) * 256 + j],
                                    e1p[(size_t)(ir + 8) * 256 + j + 1]);
        }
    }

    // ---- v2 (f16x2 pairs in smem) + v1 regs for channel 0 ----
    int d0 = dg * 13;
    if (t < 128)
        v2u[t] = cvt_h2(v2b[(size_t)d0 * NS + 2 * t], v2b[(size_t)d0 * NS + 2 * t + 1]);
    float vr0[4], vr1[4];
#pragma unroll
    for (int nt = 0; nt < 4; nt++) {
        int jg = jb * 128 + j0 + nt * 8 + (lane & 3) * 2;
        vr0[nt] = v1b[(size_t)d0 * NS + jg];
        vr1[nt] = v1b[(size_t)d0 * NS + jg + 1];
    }

    // ---- ldmatrix lane addresses (fp16 m16n8k16 fragments) ----
    int lr7 = lane & 7;
    uint32_t aRow = (uint32_t)(i0 + ((lane >> 3) & 1) * 8 + lr7);
    uint32_t aBase = sb + A_OFF + aRow * (HPCH * 2) + (uint32_t)(lane >> 4) * 16;
    uint32_t bRow = (uint32_t)(j0 + ((lane >> 4) & 1) * 8 + lr7);
    uint32_t bBase = sb + B_OFF + bRow * (HPCH * 2) + (uint32_t)((lane >> 3) & 1) * 16;

    __syncthreads();   // B + v2u ready

    float acc[2][4][4];

#pragma unroll 1
    for (int ch = 0; ch < 13; ch++) {
        int d = dg * 13 + ch;

        // ===== build full A = e2h * v2h [64 x 256 halves] =====
#pragma unroll
        for (int q = 0; q < 8; q++) {
            int row = wid + 8 * q;
            char* arow = Ab + row * (HPCH * 2);
            uint2 u;
            u.x = hmul2u(e2h0[q].x, v2u[lane * 2]);
            u.y = hmul2u(e2h0[q].y, v2u[lane * 2 + 1]);
            *(uint2*)(arow + lane * 8) = u;
            u.x = hmul2u(e2h1[q].x, v2u[64 + lane * 2]);
            u.y = hmul2u(e2h1[q].y, v2u[64 + lane * 2 + 1]);
            *(uint2*)(arow + 256 + lane * 8) = u;
        }
        __syncthreads();

#pragma unroll
        for (int m = 0; m < 2; m++)
#pragma unroll
            for (int n = 0; n < 4; n++)
#pragma unroll
                for (int c = 0; c < 4; c++) acc[m][n][c] = 0.f;

        // ===== mainloop: 16 k16-steps, 4 LDSM.x4 + 8 MMA each =====
#pragma unroll
        for (int ks = 0; ks < 16; ks++) {
            uint32_t ko = (uint32_t)(ks * 32);
            uint32_t a0[4], a1[4], b0[4], b1[4];
            ldsm_x4(a0[0], a0[1], a0[2], a0[3], aBase + ko);
            ldsm_x4(a1[0], a1[1], a1[2], a1[3], aBase + 8448 + ko);
            ldsm_x4(b0[0], b0[1], b0[2], b0[3], bBase + ko);
            ldsm_x4(b1[0], b1[1], b1[2], b1[3], bBase + 8448 + ko);
            mma_f16(acc[0][0], a0, b0[0], b0[1]);
            mma_f16(acc[0][1], a0, b0[2], b0[3]);
            mma_f16(acc[0][2], a0, b1[0], b1[1]);
            mma_f16(acc[0][3], a0, b1[2], b1[3]);
            mma_f16(acc[1][0], a1, b0[0], b0[1]);
            mma_f16(acc[1][1], a1, b0[2], b0[3]);
            mma_f16(acc[1][2], a1, b1[0], b1[1]);
            mma_f16(acc[1][3], a1, b1[2], b1[3]);
        }

        // ===== epilogue: partial[i] = sum_j e1*v1*G =====
#pragma unroll
        for (int mt = 0; mt < 2; mt++) {
            float p0 = 0.f, p1 = 0.f;
#pragma unroll
            for (int nt = 0; nt < 4; nt++) {
                float2 w0 = __half22float2(*(__half2*)&er2[mt][nt][0]);
                float2 w1 = __half22float2(*(__half2*)&er2[mt][nt][1]);
                p0 += acc[mt][nt][0] * w0.x * vr0[nt]
                    + acc[mt][nt][1] * w0.y * vr1[nt];
                p1 += acc[mt][nt][2] * w1.x * vr0[nt]
                    + acc[mt][nt][3] * w1.y * vr1[nt];
            }
            p0 += __shfl_xor_sync(0xffffffffu, p0, 1);
            p0 += __shfl_xor_sync(0xffffffffu, p0, 2);
            p1 += __shfl_xor_sync(0xffffffffu, p1, 1);
            p1 += __shfl_xor_sync(0xffffffffu, p1, 2);
            if ((lane & 3) == 0) {
                int il = i0 + mt * 16 + (lane >> 2);
                red[il * 4 + wj] = p0;
                red[(il + 8) * 4 + wj] = p1;
            }
        }
        __syncthreads();   // also guarantees all warps done reading A

        // final store + stage next channel's v1/v2
        if (t < 64) {
            float s = red[t * 4] + red[t * 4 + 1] + red[t * 4 + 2] + red[t * 4 + 3];
            int ig = ib * 64 + t;
            if (d < 64) g_numP[jb][((size_t)bh * NS + ig) * DH + d] = s;
            else        g_denP[jb][(size_t)bh * NS + ig] = s;
        }
        int d2 = d + 1;
        if (t < 128) {
            float a = (d2 < 64) ? v2b[(size_t)d2 * NS + 2 * t] : 1.f;
            float b = (d2 < 64) ? v2b[(size_t)d2 * NS + 2 * t + 1] : 1.f;
            v2u[t] = cvt_h2(a, b);
        }
#pragma unroll
        for (int nt = 0; nt < 4; nt++) {
            int jg = jb * 128 + j0 + nt * 8 + (lane & 3) * 2;
            vr0[nt] = (d2 < 64) ? v1b[(size_t)d2 * NS + jg] : 1.f;
            vr1[nt] = (d2 < 64) ? v1b[(size_t)d2 * NS + jg + 1] : 1.f;
        }
        __syncthreads();
    }
}

// ---------------- normalize: combine 2 jb partials, o = num/den ----------------
__global__ void normalize_kernel() {
    int idx = blockIdx.x * 256 + threadIdx.x;
    int dd = idx & 63;
    int i  = (idx >> 6) & 255;
    int bh = idx >> 14;
    int b = bh >> 3, h = bh & 7;
    float num = g_numP[0][idx] + g_numP[1][idx];
    float den = g_denP[0][bh * NS + i] + g_denP[1][bh * NS + i];
    g_o[(size_t)(b * 256 + i) * 512 + h * 64 + dd] = num / den;
}

extern "C" void kernel_launch(void* const* d_in, const int* in_sizes, int n_in,
                              void* d_out, int out_size) {
    const float* x     = (const float*)d_in[0];
    const float* w_qkv = (const float*)d_in[1];
    const float* w_out = (const float*)d_in[2];
    const float* qw    = (const float*)d_in[3];
    const float* k1w   = (const float*)d_in[4];
    const float* k2w   = (const float*)d_in[5];
    float* out = (float*)d_out;

    float *qkv_p = nullptr, *o_p = nullptr;
    cudaGetSymbolAddress((void**)&qkv_p, g_qkv);
    cudaGetSymbolAddress((void**)&o_p, g_o);

    cudaFuncSetAttribute(heavy_mma, cudaFuncAttributeMaxDynamicSharedMemorySize, SMEM_SZ);

    // 1) qkv = x @ w_qkv   [512,512]@[512,2560], 64x64 tiles -> 320 CTAs
    sgemm64x64<<<dim3(40, 8), 256>>>(x, w_qkv, qkv_p, 512, 2560, 512);
    // 2) split + rmsnorm + pack (warp per row)
    pack_norm<<<512, 256>>>(qw, k1w, k2w);
    // 3) e1/e2/e3
    sims_kernel<<<dim3(4, 2, 48), 256>>>();
    // 4) heavy: 5 dgroups x (ib 4 x jb 2) x bh 16 = 640 CTAs, fp16 MMA, 2 CTAs/SM
    heavy_mma<<<dim3(5, 8, 16), 256, SMEM_SZ>>>();
    // 5) normalize (sum 2 jb partials)
    normalize_kernel<<<1024, 256>>>();
    // 6) out = o @ w_out   [512,512]@[512,512], 64x64 tiles -> 64 CTAs
    sgemm64x64<<<dim3(8, 8), 256>>>(o_p, w_out, out, 512, 512, 512);
}